// round 1
// baseline (speedup 1.0000x reference)
#include <cuda_runtime.h>
#include <cuda_bf16.h>
#include <cooperative_groups.h>

namespace cg = cooperative_groups;

#define BATCH  32
#define SEQ    128
#define NSTEP  127
#define DK     128
#define NSKILL 256

#define CL   4      // cluster size (CTAs per batch)
#define SKP  64     // skills per CTA
#define NT   256    // threads in recurrent kernel
#define HST  132    // padded h row stride (floats) to kill smem bank conflicts

// ------------------------- device scratch -------------------------
__device__ float g_le[BATCH * SEQ * DK];     // learning embeddings
__device__ float g_Al[BATCH * NSTEP * DK];   // hoisted const part of lg input
__device__ float g_Ag[BATCH * NSTEP * DK];   // hoisted const part of gate input
__device__ float g_Af[BATCH * NSTEP * DK];   // hoisted const part of forget input
__device__ float g_Ap[BATCH * NSTEP * DK];   // hoisted const part of pred input

__device__ __forceinline__ float sigm(float x) { return 1.f / (1.f + __expf(-x)); }

// ------------------------------------------------------------------
// Kernel 1: le[b,s,:] = [ex | at | ans] @ W1^T + b1
// block = 128 threads, handles 8 (b,s) pairs; grid = 4096/8 = 512
// ------------------------------------------------------------------
__global__ void le_kernel(const int* __restrict__ eid, const int* __restrict__ atid,
                          const int* __restrict__ ansv,
                          const float* __restrict__ ex_table, const float* __restrict__ at_table,
                          const float* __restrict__ W1, const float* __restrict__ b1)
{
    __shared__ float X[8][256];
    __shared__ float AV[8];
    const int tid  = threadIdx.x;
    const int base = blockIdx.x * 8;

    for (int idx = tid; idx < 8 * 256; idx += 128) {
        int r = idx >> 8, c = idx & 255;
        int p = base + r;
        float v;
        if (c < 128) v = ex_table[eid[p] * DK + c];
        else         v = at_table[atid[p] * DK + (c - 128)];
        X[r][c] = v;
    }
    if (tid < 8) AV[tid] = (float)ansv[base + tid];
    __syncthreads();

    const int k = tid;
    const float4* wrow = (const float4*)(W1 + k * 384);

    // answer contribution = av * sum_j W1[k][256+j]
    float rs = 0.f;
#pragma unroll
    for (int j4 = 64; j4 < 96; ++j4) { float4 w = wrow[j4]; rs += w.x + w.y + w.z + w.w; }

    float acc[8];
    const float bk = b1[k];
#pragma unroll
    for (int r = 0; r < 8; ++r) acc[r] = bk + AV[r] * rs;

    for (int j4 = 0; j4 < 64; ++j4) {
        float4 w = wrow[j4];
#pragma unroll
        for (int r = 0; r < 8; ++r) {
            float4 x = ((const float4*)X[r])[j4];
            acc[r] = fmaf(x.x, w.x, acc[r]);
            acc[r] = fmaf(x.y, w.y, acc[r]);
            acc[r] = fmaf(x.z, w.z, acc[r]);
            acc[r] = fmaf(x.w, w.w, acc[r]);
        }
    }
#pragma unroll
    for (int r = 0; r < 8; ++r) g_le[(base + r) * DK + k] = acc[r];
}

// ------------------------------------------------------------------
// Kernel 2: hoisted per-step constants.
//   A_l[b,t] = le[b,t-1]@Wl0^T + it[b,t+1]@Wl1^T + le[b,t]@Wl2^T + bl
//   A_g[b,t] = same with Wg
//   A_f[b,t] = it[b,t+1]@Wf2^T + bf
//   A_p[b,t] = ex[b,t+1]@Wp0^T + bp
// block = 512 threads (4 groups of 128), 16 (b,t) pairs; grid = 4064/16 = 254
// ------------------------------------------------------------------
__global__ void pre_kernel(const int* __restrict__ eid, const int* __restrict__ itid,
                           const float* __restrict__ ex_table, const float* __restrict__ it_table,
                           const float* __restrict__ Wl, const float* __restrict__ bl,
                           const float* __restrict__ Wg, const float* __restrict__ bg,
                           const float* __restrict__ Wf, const float* __restrict__ bf,
                           const float* __restrict__ Wp, const float* __restrict__ bp)
{
    __shared__ float X[16][512];
    const int tid  = threadIdx.x;
    const int base = blockIdx.x * 16;   // linear (b*127 + t)

    for (int idx = tid; idx < 16 * 512; idx += 512) {
        int r = idx >> 9, c = idx & 511;
        int p = base + r;
        int b = p / NSTEP, t = p % NSTEP;
        float v;
        if (c < 128)      v = (t == 0) ? 0.f : g_le[(b * SEQ + t - 1) * DK + c];
        else if (c < 256) v = it_table[itid[b * SEQ + t + 1] * DK + (c - 128)];
        else if (c < 384) v = g_le[(b * SEQ + t) * DK + (c - 256)];
        else              v = ex_table[eid[b * SEQ + t + 1] * DK + (c - 384)];
        X[r][c] = v;
    }
    __syncthreads();

    const int g = tid >> 7, k = tid & 127;
    float acc[16];

    if (g <= 1) {
        const float* W = (g == 0) ? Wl : Wg;
        const float  bk = (g == 0) ? bl[k] : bg[k];
#pragma unroll
        for (int r = 0; r < 16; ++r) acc[r] = bk;
        const float4* wrow = (const float4*)(W + k * 512);  // cols 0..383 used
        for (int j4 = 0; j4 < 96; ++j4) {
            float4 w = wrow[j4];
#pragma unroll
            for (int r = 0; r < 16; ++r) {
                float4 x = ((const float4*)X[r])[j4];
                acc[r] = fmaf(x.x, w.x, acc[r]);
                acc[r] = fmaf(x.y, w.y, acc[r]);
                acc[r] = fmaf(x.z, w.z, acc[r]);
                acc[r] = fmaf(x.w, w.w, acc[r]);
            }
        }
        float* dst = (g == 0) ? g_Al : g_Ag;
#pragma unroll
        for (int r = 0; r < 16; ++r) dst[(base + r) * DK + k] = acc[r];
    } else if (g == 2) {
        const float bk = bf[k];
#pragma unroll
        for (int r = 0; r < 16; ++r) acc[r] = bk;
        const float4* wrow = (const float4*)(Wf + k * 384 + 256);
        for (int j4 = 0; j4 < 32; ++j4) {
            float4 w = wrow[j4];
#pragma unroll
            for (int r = 0; r < 16; ++r) {
                float4 x = ((const float4*)(X[r] + 128))[j4];
                acc[r] = fmaf(x.x, w.x, acc[r]);
                acc[r] = fmaf(x.y, w.y, acc[r]);
                acc[r] = fmaf(x.z, w.z, acc[r]);
                acc[r] = fmaf(x.w, w.w, acc[r]);
            }
        }
#pragma unroll
        for (int r = 0; r < 16; ++r) g_Af[(base + r) * DK + k] = acc[r];
    } else {
        const float bk = bp[k];
#pragma unroll
        for (int r = 0; r < 16; ++r) acc[r] = bk;
        const float4* wrow = (const float4*)(Wp + k * 256);
        for (int j4 = 0; j4 < 32; ++j4) {
            float4 w = wrow[j4];
#pragma unroll
            for (int r = 0; r < 16; ++r) {
                float4 x = ((const float4*)(X[r] + 384))[j4];
                acc[r] = fmaf(x.x, w.x, acc[r]);
                acc[r] = fmaf(x.y, w.y, acc[r]);
                acc[r] = fmaf(x.z, w.z, acc[r]);
                acc[r] = fmaf(x.w, w.w, acc[r]);
            }
        }
#pragma unroll
        for (int r = 0; r < 16; ++r) g_Ap[(base + r) * DK + k] = acc[r];
    }
}

// ------------------------------------------------------------------
// Kernel 3: recurrent loop. One cluster of 4 CTAs per batch, each CTA
// owns 64 skills. h state + Wf0^T in SMEM; h_tilde reduced via DSMEM
// mailboxes with one cluster.sync per step (double buffered).
// ------------------------------------------------------------------
static constexpr int SM_H    = 0;
static constexpr int SM_WT   = SM_H + SKP * HST;           // 8448
static constexpr int SM_RED  = SM_WT + DK * DK;            // +16384
static constexpr int SM_LG   = SM_RED + 16 * DK;           // +2048
static constexpr int SM_CF   = SM_LG + DK;
static constexpr int SM_HT   = SM_CF + DK;
static constexpr int SM_LGV  = SM_HT + DK;
static constexpr int SM_GTV  = SM_LGV + DK;
static constexpr int SM_MAIL = SM_GTV + DK;                // 2*DK
static constexpr int SM_KVT  = SM_MAIL + 2 * DK;
static constexpr int SM_KVN  = SM_KVT + SKP;
static constexpr int SM_TOT  = SM_KVN + SKP;               // floats
static constexpr int SMEM_BYTES = SM_TOT * 4;              // ~111.6 KB

__global__ void __cluster_dims__(CL, 1, 1) __launch_bounds__(NT, 1)
recur_kernel(const int* __restrict__ eid, const float* __restrict__ qmat,
             const float* __restrict__ Wl, const float* __restrict__ Wg,
             const float* __restrict__ Wf, const float* __restrict__ Wp,
             const float* __restrict__ h0, float* __restrict__ out)
{
    extern __shared__ float sm[];
    float* hS   = sm + SM_H;
    float* wT   = sm + SM_WT;    // Wf0 transposed: wT[j*DK + k] = Wf[k*384 + j]
    float* red  = sm + SM_RED;
    float* LG   = sm + SM_LG;
    float* cf   = sm + SM_CF;
    float* htil = sm + SM_HT;
    float* lgv  = sm + SM_LGV;
    float* gtv  = sm + SM_GTV;
    float* mail = sm + SM_MAIL;
    float* kvt  = sm + SM_KVT;
    float* kvn  = sm + SM_KVN;

    cg::cluster_group cluster = cg::this_cluster();
    const int tid   = threadIdx.x;
    const int b     = blockIdx.x / CL;
    const int r     = blockIdx.x % CL;       // == cluster rank for 1D
    const int sBase = r * SKP;

    // ---- prologue: load Wf0^T, h0 slice, kv[:,0] ----
    for (int idx = tid; idx < DK * DK; idx += NT) {
        int j = idx >> 7, k = idx & 127;
        wT[idx] = Wf[k * 384 + j];
    }
    for (int idx = tid; idx < SKP * DK; idx += NT) {
        int s = idx >> 7, k = idx & 127;
        hS[s * HST + k] = h0[(sBase + s) * DK + k];
    }
    if (tid < SKP) kvt[tid] = qmat[eid[b * SEQ] * NSKILL + sBase + tid];
    __syncthreads();

    // initial h_tilde partial -> mail[1]
    if (tid < DK) {
        float a = 0.f;
        for (int s = 0; s < SKP; ++s) a = fmaf(kvt[s], hS[s * HST + tid], a);
        mail[DK + tid] = a;
    }
    cluster.sync();
    if (tid < DK) {
        float a = 0.f;
#pragma unroll
        for (int rr = 0; rr < CL; ++rr) {
            const float* m = (const float*)cluster.map_shared_rank((void*)mail, rr);
            a += m[DK + tid];
        }
        htil[tid] = a;
    }
    __syncthreads();

    const int kG = tid & 15;         // 16 groups of 8 output cols
    const int sG = tid >> 4;         // 16 groups of 4 skill rows
    const float* wT8   = wT + kG * 8;
    const float* hrow0 = hS + (sG * 4) * HST;

    for (int t = 0; t < NSTEP; ++t) {
        // ---- phase 1: facc = h_pre @ Wf0^T (64x128 per CTA) ----
        float facc[4][8];
#pragma unroll
        for (int i = 0; i < 4; ++i)
#pragma unroll
            for (int c = 0; c < 8; ++c) facc[i][c] = 0.f;

#pragma unroll 2
        for (int j = 0; j < DK; ++j) {
            float wv[8];
            float4 w0 = *(const float4*)(wT8 + j * DK);
            float4 w1 = *(const float4*)(wT8 + j * DK + 4);
            wv[0] = w0.x; wv[1] = w0.y; wv[2] = w0.z; wv[3] = w0.w;
            wv[4] = w1.x; wv[5] = w1.y; wv[6] = w1.z; wv[7] = w1.w;
            float hv[4];
#pragma unroll
            for (int i = 0; i < 4; ++i) hv[i] = hrow0[i * HST + j];
#pragma unroll
            for (int i = 0; i < 4; ++i)
#pragma unroll
                for (int c = 0; c < 8; ++c)
                    facc[i][c] = fmaf(hv[i], wv[c], facc[i][c]);
        }

        // ---- phase 2: lg/gate matvecs from h_tilde_pre (global W, L2 hot) ----
        {
            const int pt = (b * NSTEP + t) * DK;
            if (tid < DK) {
                const int k = tid;
                float a = g_Al[pt + k];
                const float4* w = (const float4*)(Wl + k * 512 + 384);
#pragma unroll
                for (int j4 = 0; j4 < 32; ++j4) {
                    float4 wv = w[j4];
                    float4 hv = *(const float4*)(htil + j4 * 4);
                    a = fmaf(hv.x, wv.x, a); a = fmaf(hv.y, wv.y, a);
                    a = fmaf(hv.z, wv.z, a); a = fmaf(hv.w, wv.w, a);
                }
                lgv[k] = a;
            } else {
                const int k = tid - DK;
                float a = g_Ag[pt + k];
                const float4* w = (const float4*)(Wg + k * 512 + 384);
#pragma unroll
                for (int j4 = 0; j4 < 32; ++j4) {
                    float4 wv = w[j4];
                    float4 hv = *(const float4*)(htil + j4 * 4);
                    a = fmaf(hv.x, wv.x, a); a = fmaf(hv.y, wv.y, a);
                    a = fmaf(hv.z, wv.z, a); a = fmaf(hv.w, wv.w, a);
                }
                gtv[k] = a;
            }
        }
        __syncthreads();

        // ---- phase 3: LG = sigm(gate)*sigm(2*lg)  [ (tanh+1)/2 == sigm(2x) ]
        //      plus load kv_next
        if (tid < DK) {
            LG[tid] = sigm(gtv[tid]) * sigm(2.f * lgv[tid]);
        } else if (tid < DK + SKP) {
            const int s = tid - DK;
            kvn[s] = qmat[eid[b * SEQ + t + 1] * NSKILL + sBase + s];
        }
        __syncthreads();

        // ---- phase 4: cf = A_f + LG @ Wf1^T ----
        if (tid < DK) {
            const int k = tid;
            float a = g_Af[(b * NSTEP + t) * DK + k];
            const float4* w = (const float4*)(Wf + k * 384 + 128);
#pragma unroll
            for (int j4 = 0; j4 < 32; ++j4) {
                float4 wv = w[j4];
                float4 hv = *(const float4*)(LG + j4 * 4);
                a = fmaf(hv.x, wv.x, a); a = fmaf(hv.y, wv.y, a);
                a = fmaf(hv.z, wv.z, a); a = fmaf(hv.w, wv.w, a);
            }
            cf[k] = a;
        }
        __syncthreads();

        // ---- phase 5: f, h update, partial h_tilde ----
        float pk[8];
#pragma unroll
        for (int c = 0; c < 8; ++c) pk[c] = 0.f;
#pragma unroll
        for (int i = 0; i < 4; ++i) {
            const int s = sG * 4 + i;
            const float kt = kvt[s], kn = kvn[s];
            float* hr = hS + s * HST + kG * 8;
#pragma unroll
            for (int c = 0; c < 8; ++c) {
                const int k = kG * 8 + c;
                float f  = sigm(facc[i][c] + cf[k]);
                float hn = fmaf(f, hr[c], kt * LG[k]);
                hr[c] = hn;
                pk[c] = fmaf(kn, hn, pk[c]);
            }
        }
#pragma unroll
        for (int c = 0; c < 8; ++c) red[sG * DK + kG * 8 + c] = pk[c];
        __syncthreads();

        // ---- phase 6: CTA-local reduce -> mailbox ----
        float* mb = mail + (t & 1) * DK;
        if (tid < DK) {
            float a = 0.f;
#pragma unroll
            for (int g2 = 0; g2 < 16; ++g2) a += red[g2 * DK + tid];
            mb[tid] = a;
        }
        cluster.sync();

        // ---- phase 7: cluster reduce -> new h_tilde ----
        if (tid < DK) {
            float a = 0.f;
#pragma unroll
            for (int rr = 0; rr < CL; ++rr) {
                const float* m = (const float*)cluster.map_shared_rank((void*)mail, rr);
                a += m[(t & 1) * DK + tid];
            }
            htil[tid] = a;
        }
        __syncthreads();

        // ---- phase 8: prediction (32 outputs per rank) + kvt <- kvn ----
        if (tid < 32) {
            const int k = r * 32 + tid;
            float a = g_Ap[(b * NSTEP + t) * DK + k];
            const float4* w = (const float4*)(Wp + k * 256 + 128);
#pragma unroll
            for (int j4 = 0; j4 < 32; ++j4) {
                float4 wv = w[j4];
                float4 hv = *(const float4*)(htil + j4 * 4);
                a = fmaf(hv.x, wv.x, a); a = fmaf(hv.y, wv.y, a);
                a = fmaf(hv.z, wv.z, a); a = fmaf(hv.w, wv.w, a);
            }
            out[(b * NSTEP + t) * DK + k] = sigm(a);
        } else if (tid < 32 + SKP) {
            kvt[tid - 32] = kvn[tid - 32];
        }
        // kvn rewritten only after phase-2 __syncthreads next iter -> safe
    }
    cluster.sync();  // keep SMEM alive for any lagging DSMEM readers
}

// ------------------------------------------------------------------
extern "C" void kernel_launch(void* const* d_in, const int* in_sizes, int n_in,
                              void* d_out, int out_size)
{
    const int*   eid      = (const int*)d_in[0];
    const int*   atid     = (const int*)d_in[1];
    const int*   itid     = (const int*)d_in[2];
    const int*   ansv     = (const int*)d_in[3];
    const float* qmat     = (const float*)d_in[4];
    const float* ex_table = (const float*)d_in[5];
    const float* at_table = (const float*)d_in[6];
    const float* it_table = (const float*)d_in[7];
    const float* W1       = (const float*)d_in[8];
    const float* b1       = (const float*)d_in[9];
    const float* Wl       = (const float*)d_in[10];
    const float* bl       = (const float*)d_in[11];
    const float* Wg       = (const float*)d_in[12];
    const float* bg       = (const float*)d_in[13];
    const float* Wf       = (const float*)d_in[14];
    const float* bf       = (const float*)d_in[15];
    const float* Wp       = (const float*)d_in[16];
    const float* bp       = (const float*)d_in[17];
    const float* h0       = (const float*)d_in[18];
    float* out = (float*)d_out;

    cudaFuncSetAttribute(recur_kernel, cudaFuncAttributeMaxDynamicSharedMemorySize, SMEM_BYTES);

    le_kernel<<<(BATCH * SEQ) / 8, 128>>>(eid, atid, ansv, ex_table, at_table, W1, b1);
    pre_kernel<<<(BATCH * NSTEP) / 16, 512>>>(eid, itid, ex_table, it_table,
                                              Wl, bl, Wg, bg, Wf, bf, Wp, bp);
    recur_kernel<<<BATCH * CL, NT, SMEM_BYTES>>>(eid, qmat, Wl, Wg, Wf, Wp, h0, out);
}

// round 2
// speedup vs baseline: 1.0007x; 1.0007x over previous
#include <cuda_runtime.h>
#include <cuda_bf16.h>
#include <cooperative_groups.h>

namespace cg = cooperative_groups;

#define BATCH  32
#define SEQ    128
#define NSTEP  127
#define DK     128
#define NSKILL 256

#define CL   4      // cluster size (CTAs per batch)
#define SKP  64     // skills per CTA
#define NT   256    // threads in recurrent kernel
#define HST  132    // padded h row stride (floats) to kill smem bank conflicts

// ------------------------- device scratch -------------------------
__device__ float g_le[BATCH * SEQ * DK];     // learning embeddings
__device__ float g_Al[BATCH * NSTEP * DK];   // hoisted const part of lg input
__device__ float g_Ag[BATCH * NSTEP * DK];   // hoisted const part of gate input
__device__ float g_Af[BATCH * NSTEP * DK];   // hoisted const part of forget input
__device__ float g_Ap[BATCH * NSTEP * DK];   // hoisted const part of pred input

__device__ __forceinline__ float sigm(float x) { return 1.f / (1.f + __expf(-x)); }

// ------------------------------------------------------------------
// Kernel 1: le[b,s,:] = [ex | at | ans] @ W1^T + b1
// block = 128 threads, handles 8 (b,s) pairs; grid = 4096/8 = 512
// ------------------------------------------------------------------
__global__ void le_kernel(const int* __restrict__ eid, const int* __restrict__ atid,
                          const int* __restrict__ ansv,
                          const float* __restrict__ ex_table, const float* __restrict__ at_table,
                          const float* __restrict__ W1, const float* __restrict__ b1)
{
    __shared__ float X[8][256];
    __shared__ float AV[8];
    const int tid  = threadIdx.x;
    const int base = blockIdx.x * 8;

    for (int idx = tid; idx < 8 * 256; idx += 128) {
        int r = idx >> 8, c = idx & 255;
        int p = base + r;
        float v;
        if (c < 128) v = ex_table[eid[p] * DK + c];
        else         v = at_table[atid[p] * DK + (c - 128)];
        X[r][c] = v;
    }
    if (tid < 8) AV[tid] = (float)ansv[base + tid];
    __syncthreads();

    const int k = tid;
    const float4* wrow = (const float4*)(W1 + k * 384);

    // answer contribution = av * sum_j W1[k][256+j]
    float rs = 0.f;
#pragma unroll
    for (int j4 = 64; j4 < 96; ++j4) { float4 w = wrow[j4]; rs += w.x + w.y + w.z + w.w; }

    float acc[8];
    const float bk = b1[k];
#pragma unroll
    for (int r = 0; r < 8; ++r) acc[r] = bk + AV[r] * rs;

    for (int j4 = 0; j4 < 64; ++j4) {
        float4 w = wrow[j4];
#pragma unroll
        for (int r = 0; r < 8; ++r) {
            float4 x = ((const float4*)X[r])[j4];
            acc[r] = fmaf(x.x, w.x, acc[r]);
            acc[r] = fmaf(x.y, w.y, acc[r]);
            acc[r] = fmaf(x.z, w.z, acc[r]);
            acc[r] = fmaf(x.w, w.w, acc[r]);
        }
    }
#pragma unroll
    for (int r = 0; r < 8; ++r) g_le[(base + r) * DK + k] = acc[r];
}

// ------------------------------------------------------------------
// Kernel 2: hoisted per-step constants.
//   A_l[b,t] = le[b,t-1]@Wl0^T + it[b,t+1]@Wl1^T + le[b,t]@Wl2^T + bl
//   A_g[b,t] = same with Wg
//   A_f[b,t] = it[b,t+1]@Wf2^T + bf
//   A_p[b,t] = ex[b,t+1]@Wp0^T + bp
// block = 512 threads (4 groups of 128), 16 (b,t) pairs; grid = 4064/16 = 254
// ------------------------------------------------------------------
__global__ void pre_kernel(const int* __restrict__ eid, const int* __restrict__ itid,
                           const float* __restrict__ ex_table, const float* __restrict__ it_table,
                           const float* __restrict__ Wl, const float* __restrict__ bl,
                           const float* __restrict__ Wg, const float* __restrict__ bg,
                           const float* __restrict__ Wf, const float* __restrict__ bf,
                           const float* __restrict__ Wp, const float* __restrict__ bp)
{
    __shared__ float X[16][512];
    const int tid  = threadIdx.x;
    const int base = blockIdx.x * 16;   // linear (b*127 + t)

    for (int idx = tid; idx < 16 * 512; idx += 512) {
        int r = idx >> 9, c = idx & 511;
        int p = base + r;
        int b = p / NSTEP, t = p % NSTEP;
        float v;
        if (c < 128)      v = (t == 0) ? 0.f : g_le[(b * SEQ + t - 1) * DK + c];
        else if (c < 256) v = it_table[itid[b * SEQ + t + 1] * DK + (c - 128)];
        else if (c < 384) v = g_le[(b * SEQ + t) * DK + (c - 256)];
        else              v = ex_table[eid[b * SEQ + t + 1] * DK + (c - 384)];
        X[r][c] = v;
    }
    __syncthreads();

    const int g = tid >> 7, k = tid & 127;
    float acc[16];

    if (g <= 1) {
        const float* W = (g == 0) ? Wl : Wg;
        const float  bk = (g == 0) ? bl[k] : bg[k];
#pragma unroll
        for (int r = 0; r < 16; ++r) acc[r] = bk;
        const float4* wrow = (const float4*)(W + k * 512);  // cols 0..383 used
        for (int j4 = 0; j4 < 96; ++j4) {
            float4 w = wrow[j4];
#pragma unroll
            for (int r = 0; r < 16; ++r) {
                float4 x = ((const float4*)X[r])[j4];
                acc[r] = fmaf(x.x, w.x, acc[r]);
                acc[r] = fmaf(x.y, w.y, acc[r]);
                acc[r] = fmaf(x.z, w.z, acc[r]);
                acc[r] = fmaf(x.w, w.w, acc[r]);
            }
        }
        float* dst = (g == 0) ? g_Al : g_Ag;
#pragma unroll
        for (int r = 0; r < 16; ++r) dst[(base + r) * DK + k] = acc[r];
    } else if (g == 2) {
        const float bk = bf[k];
#pragma unroll
        for (int r = 0; r < 16; ++r) acc[r] = bk;
        const float4* wrow = (const float4*)(Wf + k * 384 + 256);
        for (int j4 = 0; j4 < 32; ++j4) {
            float4 w = wrow[j4];
#pragma unroll
            for (int r = 0; r < 16; ++r) {
                float4 x = ((const float4*)(X[r] + 128))[j4];
                acc[r] = fmaf(x.x, w.x, acc[r]);
                acc[r] = fmaf(x.y, w.y, acc[r]);
                acc[r] = fmaf(x.z, w.z, acc[r]);
                acc[r] = fmaf(x.w, w.w, acc[r]);
            }
        }
#pragma unroll
        for (int r = 0; r < 16; ++r) g_Af[(base + r) * DK + k] = acc[r];
    } else {
        const float bk = bp[k];
#pragma unroll
        for (int r = 0; r < 16; ++r) acc[r] = bk;
        const float4* wrow = (const float4*)(Wp + k * 256);
        for (int j4 = 0; j4 < 32; ++j4) {
            float4 w = wrow[j4];
#pragma unroll
            for (int r = 0; r < 16; ++r) {
                float4 x = ((const float4*)(X[r] + 384))[j4];
                acc[r] = fmaf(x.x, w.x, acc[r]);
                acc[r] = fmaf(x.y, w.y, acc[r]);
                acc[r] = fmaf(x.z, w.z, acc[r]);
                acc[r] = fmaf(x.w, w.w, acc[r]);
            }
        }
#pragma unroll
        for (int r = 0; r < 16; ++r) g_Ap[(base + r) * DK + k] = acc[r];
    }
}

// ------------------------------------------------------------------
// Kernel 3: recurrent loop. One cluster of 4 CTAs per batch, each CTA
// owns 64 skills. h state + Wf0^T in SMEM; h_tilde reduced via DSMEM
// mailboxes with one cluster.sync per step (double buffered).
// ------------------------------------------------------------------
static constexpr int SM_H    = 0;
static constexpr int SM_WT   = SM_H + SKP * HST;           // 8448
static constexpr int SM_RED  = SM_WT + DK * DK;            // +16384
static constexpr int SM_LG   = SM_RED + 16 * DK;           // +2048
static constexpr int SM_CF   = SM_LG + DK;
static constexpr int SM_HT   = SM_CF + DK;
static constexpr int SM_LGV  = SM_HT + DK;
static constexpr int SM_GTV  = SM_LGV + DK;
static constexpr int SM_MAIL = SM_GTV + DK;                // 2*DK
static constexpr int SM_KVT  = SM_MAIL + 2 * DK;
static constexpr int SM_KVN  = SM_KVT + SKP;
static constexpr int SM_TOT  = SM_KVN + SKP;               // floats
static constexpr int SMEM_BYTES = SM_TOT * 4;              // ~111.6 KB

__global__ void __cluster_dims__(CL, 1, 1) __launch_bounds__(NT, 1)
recur_kernel(const int* __restrict__ eid, const float* __restrict__ qmat,
             const float* __restrict__ Wl, const float* __restrict__ Wg,
             const float* __restrict__ Wf, const float* __restrict__ Wp,
             const float* __restrict__ h0, float* __restrict__ out)
{
    extern __shared__ float sm[];
    float* hS   = sm + SM_H;
    float* wT   = sm + SM_WT;    // Wf0 transposed: wT[j*DK + k] = Wf[k*384 + j]
    float* red  = sm + SM_RED;
    float* LG   = sm + SM_LG;
    float* cf   = sm + SM_CF;
    float* htil = sm + SM_HT;
    float* lgv  = sm + SM_LGV;
    float* gtv  = sm + SM_GTV;
    float* mail = sm + SM_MAIL;
    float* kvt  = sm + SM_KVT;
    float* kvn  = sm + SM_KVN;

    cg::cluster_group cluster = cg::this_cluster();
    const int tid   = threadIdx.x;
    const int b     = blockIdx.x / CL;
    const int r     = blockIdx.x % CL;       // == cluster rank for 1D
    const int sBase = r * SKP;

    // ---- prologue: load Wf0^T, h0 slice, kv[:,0] ----
    for (int idx = tid; idx < DK * DK; idx += NT) {
        int j = idx >> 7, k = idx & 127;
        wT[idx] = Wf[k * 384 + j];
    }
    for (int idx = tid; idx < SKP * DK; idx += NT) {
        int s = idx >> 7, k = idx & 127;
        hS[s * HST + k] = h0[(sBase + s) * DK + k];
    }
    if (tid < SKP) kvt[tid] = qmat[eid[b * SEQ] * NSKILL + sBase + tid];
    __syncthreads();

    // initial h_tilde partial -> mail[1]
    if (tid < DK) {
        float a = 0.f;
        for (int s = 0; s < SKP; ++s) a = fmaf(kvt[s], hS[s * HST + tid], a);
        mail[DK + tid] = a;
    }
    cluster.sync();
    if (tid < DK) {
        float a = 0.f;
#pragma unroll
        for (int rr = 0; rr < CL; ++rr) {
            const float* m = (const float*)cluster.map_shared_rank((void*)mail, rr);
            a += m[DK + tid];
        }
        htil[tid] = a;
    }
    __syncthreads();

    const int kG = tid & 15;         // 16 groups of 8 output cols
    const int sG = tid >> 4;         // 16 groups of 4 skill rows
    const float* wT8   = wT + kG * 8;
    const float* hrow0 = hS + (sG * 4) * HST;

    for (int t = 0; t < NSTEP; ++t) {
        // ---- phase 1: facc = h_pre @ Wf0^T (64x128 per CTA) ----
        float facc[4][8];
#pragma unroll
        for (int i = 0; i < 4; ++i)
#pragma unroll
            for (int c = 0; c < 8; ++c) facc[i][c] = 0.f;

#pragma unroll 2
        for (int j = 0; j < DK; ++j) {
            float wv[8];
            float4 w0 = *(const float4*)(wT8 + j * DK);
            float4 w1 = *(const float4*)(wT8 + j * DK + 4);
            wv[0] = w0.x; wv[1] = w0.y; wv[2] = w0.z; wv[3] = w0.w;
            wv[4] = w1.x; wv[5] = w1.y; wv[6] = w1.z; wv[7] = w1.w;
            float hv[4];
#pragma unroll
            for (int i = 0; i < 4; ++i) hv[i] = hrow0[i * HST + j];
#pragma unroll
            for (int i = 0; i < 4; ++i)
#pragma unroll
                for (int c = 0; c < 8; ++c)
                    facc[i][c] = fmaf(hv[i], wv[c], facc[i][c]);
        }

        // ---- phase 2: lg/gate matvecs from h_tilde_pre (global W, L2 hot) ----
        {
            const int pt = (b * NSTEP + t) * DK;
            if (tid < DK) {
                const int k = tid;
                float a = g_Al[pt + k];
                const float4* w = (const float4*)(Wl + k * 512 + 384);
#pragma unroll
                for (int j4 = 0; j4 < 32; ++j4) {
                    float4 wv = w[j4];
                    float4 hv = *(const float4*)(htil + j4 * 4);
                    a = fmaf(hv.x, wv.x, a); a = fmaf(hv.y, wv.y, a);
                    a = fmaf(hv.z, wv.z, a); a = fmaf(hv.w, wv.w, a);
                }
                lgv[k] = a;
            } else {
                const int k = tid - DK;
                float a = g_Ag[pt + k];
                const float4* w = (const float4*)(Wg + k * 512 + 384);
#pragma unroll
                for (int j4 = 0; j4 < 32; ++j4) {
                    float4 wv = w[j4];
                    float4 hv = *(const float4*)(htil + j4 * 4);
                    a = fmaf(hv.x, wv.x, a); a = fmaf(hv.y, wv.y, a);
                    a = fmaf(hv.z, wv.z, a); a = fmaf(hv.w, wv.w, a);
                }
                gtv[k] = a;
            }
        }
        __syncthreads();

        // ---- phase 3: LG = sigm(gate)*sigm(2*lg)  [ (tanh+1)/2 == sigm(2x) ]
        //      plus load kv_next
        if (tid < DK) {
            LG[tid] = sigm(gtv[tid]) * sigm(2.f * lgv[tid]);
        } else if (tid < DK + SKP) {
            const int s = tid - DK;
            kvn[s] = qmat[eid[b * SEQ + t + 1] * NSKILL + sBase + s];
        }
        __syncthreads();

        // ---- phase 4: cf = A_f + LG @ Wf1^T ----
        if (tid < DK) {
            const int k = tid;
            float a = g_Af[(b * NSTEP + t) * DK + k];
            const float4* w = (const float4*)(Wf + k * 384 + 128);
#pragma unroll
            for (int j4 = 0; j4 < 32; ++j4) {
                float4 wv = w[j4];
                float4 hv = *(const float4*)(LG + j4 * 4);
                a = fmaf(hv.x, wv.x, a); a = fmaf(hv.y, wv.y, a);
                a = fmaf(hv.z, wv.z, a); a = fmaf(hv.w, wv.w, a);
            }
            cf[k] = a;
        }
        __syncthreads();

        // ---- phase 5: f, h update, partial h_tilde ----
        float pk[8];
#pragma unroll
        for (int c = 0; c < 8; ++c) pk[c] = 0.f;
#pragma unroll
        for (int i = 0; i < 4; ++i) {
            const int s = sG * 4 + i;
            const float kt = kvt[s], kn = kvn[s];
            float* hr = hS + s * HST + kG * 8;
#pragma unroll
            for (int c = 0; c < 8; ++c) {
                const int k = kG * 8 + c;
                float f  = sigm(facc[i][c] + cf[k]);
                float hn = fmaf(f, hr[c], kt * LG[k]);
                hr[c] = hn;
                pk[c] = fmaf(kn, hn, pk[c]);
            }
        }
#pragma unroll
        for (int c = 0; c < 8; ++c) red[sG * DK + kG * 8 + c] = pk[c];
        __syncthreads();

        // ---- phase 6: CTA-local reduce -> mailbox ----
        float* mb = mail + (t & 1) * DK;
        if (tid < DK) {
            float a = 0.f;
#pragma unroll
            for (int g2 = 0; g2 < 16; ++g2) a += red[g2 * DK + tid];
            mb[tid] = a;
        }
        cluster.sync();

        // ---- phase 7: cluster reduce -> new h_tilde ----
        if (tid < DK) {
            float a = 0.f;
#pragma unroll
            for (int rr = 0; rr < CL; ++rr) {
                const float* m = (const float*)cluster.map_shared_rank((void*)mail, rr);
                a += m[(t & 1) * DK + tid];
            }
            htil[tid] = a;
        }
        __syncthreads();

        // ---- phase 8: prediction (32 outputs per rank) + kvt <- kvn ----
        if (tid < 32) {
            const int k = r * 32 + tid;
            float a = g_Ap[(b * NSTEP + t) * DK + k];
            const float4* w = (const float4*)(Wp + k * 256 + 128);
#pragma unroll
            for (int j4 = 0; j4 < 32; ++j4) {
                float4 wv = w[j4];
                float4 hv = *(const float4*)(htil + j4 * 4);
                a = fmaf(hv.x, wv.x, a); a = fmaf(hv.y, wv.y, a);
                a = fmaf(hv.z, wv.z, a); a = fmaf(hv.w, wv.w, a);
            }
            out[(b * NSTEP + t) * DK + k] = sigm(a);
        } else if (tid < 32 + SKP) {
            kvt[tid - 32] = kvn[tid - 32];
        }
        // kvn rewritten only after phase-2 __syncthreads next iter -> safe
    }
    cluster.sync();  // keep SMEM alive for any lagging DSMEM readers
}

// ------------------------------------------------------------------
extern "C" void kernel_launch(void* const* d_in, const int* in_sizes, int n_in,
                              void* d_out, int out_size)
{
    const int*   eid      = (const int*)d_in[0];
    const int*   atid     = (const int*)d_in[1];
    const int*   itid     = (const int*)d_in[2];
    const int*   ansv     = (const int*)d_in[3];
    const float* qmat     = (const float*)d_in[4];
    const float* ex_table = (const float*)d_in[5];
    const float* at_table = (const float*)d_in[6];
    const float* it_table = (const float*)d_in[7];
    const float* W1       = (const float*)d_in[8];
    const float* b1       = (const float*)d_in[9];
    const float* Wl       = (const float*)d_in[10];
    const float* bl       = (const float*)d_in[11];
    const float* Wg       = (const float*)d_in[12];
    const float* bg       = (const float*)d_in[13];
    const float* Wf       = (const float*)d_in[14];
    const float* bf       = (const float*)d_in[15];
    const float* Wp       = (const float*)d_in[16];
    const float* bp       = (const float*)d_in[17];
    const float* h0       = (const float*)d_in[18];
    float* out = (float*)d_out;

    cudaFuncSetAttribute(recur_kernel, cudaFuncAttributeMaxDynamicSharedMemorySize, SMEM_BYTES);

    le_kernel<<<(BATCH * SEQ) / 8, 128>>>(eid, atid, ansv, ex_table, at_table, W1, b1);
    pre_kernel<<<(BATCH * NSTEP) / 16, 512>>>(eid, itid, ex_table, it_table,
                                              Wl, bl, Wg, bg, Wf, bf, Wp, bp);
    recur_kernel<<<BATCH * CL, NT, SMEM_BYTES>>>(eid, qmat, Wl, Wg, Wf, Wp, h0, out);
}

// round 3
// speedup vs baseline: 1.3690x; 1.3680x over previous
#include <cuda_runtime.h>
#include <cuda_bf16.h>

#define BATCH  32
#define SEQ    128
#define NSTEP  127
#define DK     128
#define NSKILL 256

#define CL   4      // cluster size (CTAs per batch)
#define SKP  64     // skills per CTA
#define NT   256    // threads in recurrent kernel
#define HST  132    // padded h row stride (floats)
#define WST  132    // padded small-weight row stride (floats)

// ------------------------- device scratch -------------------------
__device__ float g_le[BATCH * SEQ * DK];
__device__ float g_Al[BATCH * NSTEP * DK];
__device__ float g_Ag[BATCH * NSTEP * DK];
__device__ float g_Af[BATCH * NSTEP * DK];
__device__ float g_Ap[BATCH * NSTEP * DK];

__device__ __forceinline__ float sigm(float x) { return 1.f / (1.f + __expf(-x)); }

// ---------- packed f32x2 helpers ----------
__device__ __forceinline__ unsigned long long fma2(unsigned long long a,
                                                   unsigned long long b,
                                                   unsigned long long c) {
    unsigned long long d;
    asm("fma.rn.f32x2 %0, %1, %2, %3;" : "=l"(d) : "l"(a), "l"(b), "l"(c));
    return d;
}
__device__ __forceinline__ unsigned long long f2pack(float x, float y) {
    unsigned long long u;
    asm("mov.b64 %0, {%1, %2};" : "=l"(u) : "f"(x), "f"(y));
    return u;
}
__device__ __forceinline__ float2 f2unpack(unsigned long long u) {
    float2 r;
    asm("mov.b64 {%0, %1}, %2;" : "=f"(r.x), "=f"(r.y) : "l"(u));
    return r;
}

// ---------- cluster / mbarrier helpers ----------
__device__ __forceinline__ unsigned smem_u32(const void* p) {
    unsigned a;
    asm("{ .reg .u64 t; cvta.to.shared.u64 t, %1; cvt.u32.u64 %0, t; }" : "=r"(a) : "l"(p));
    return a;
}
__device__ __forceinline__ unsigned mapa_rank(unsigned a, int rank) {
    unsigned d;
    asm("mapa.shared::cluster.u32 %0, %1, %2;" : "=r"(d) : "r"(a), "r"(rank));
    return d;
}
__device__ __forceinline__ void st_cluster_f32(unsigned a, float v) {
    asm volatile("st.shared::cluster.f32 [%0], %1;" :: "r"(a), "f"(v) : "memory");
}
__device__ __forceinline__ void mbar_init(unsigned a, unsigned cnt) {
    asm volatile("mbarrier.init.shared.b64 [%0], %1;" :: "r"(a), "r"(cnt) : "memory");
}
__device__ __forceinline__ void arrive_cluster(unsigned a) {
    asm volatile("mbarrier.arrive.release.cluster.shared::cluster.b64 _, [%0];"
                 :: "r"(a) : "memory");
}
__device__ __forceinline__ void wait_parity_cluster(unsigned a, unsigned ph) {
    unsigned done;
    asm volatile(
        "{\n\t.reg .pred p;\n\t"
        "mbarrier.try_wait.parity.acquire.cluster.shared::cta.b64 p, [%1], %2;\n\t"
        "selp.b32 %0, 1, 0, p;\n\t}"
        : "=r"(done) : "r"(a), "r"(ph) : "memory");
    if (!done) {
        asm volatile(
            "{\n\t.reg .pred P1;\n\t"
            "W_%=:\n\t"
            "mbarrier.try_wait.parity.acquire.cluster.shared::cta.b64 P1, [%0], %1, 0x989680;\n\t"
            "@P1 bra.uni D_%=;\n\t"
            "bra.uni W_%=;\n\t"
            "D_%=:\n\t}"
            :: "r"(a), "r"(ph) : "memory");
    }
}
__device__ __forceinline__ void cluster_sync_all() {
    asm volatile("barrier.cluster.arrive.aligned;" ::: "memory");
    asm volatile("barrier.cluster.wait.aligned;" ::: "memory");
}
__device__ __forceinline__ unsigned my_cluster_rank() {
    unsigned r;
    asm("mov.u32 %0, %%cluster_ctarank;" : "=r"(r));
    return r;
}

// ------------------------------------------------------------------
// Kernel 1: le[b,s,:] = [ex | at | ans] @ W1^T + b1    (unchanged)
// ------------------------------------------------------------------
__global__ void le_kernel(const int* __restrict__ eid, const int* __restrict__ atid,
                          const int* __restrict__ ansv,
                          const float* __restrict__ ex_table, const float* __restrict__ at_table,
                          const float* __restrict__ W1, const float* __restrict__ b1)
{
    __shared__ float X[8][256];
    __shared__ float AV[8];
    const int tid  = threadIdx.x;
    const int base = blockIdx.x * 8;

    for (int idx = tid; idx < 8 * 256; idx += 128) {
        int r = idx >> 8, c = idx & 255;
        int p = base + r;
        float v;
        if (c < 128) v = ex_table[eid[p] * DK + c];
        else         v = at_table[atid[p] * DK + (c - 128)];
        X[r][c] = v;
    }
    if (tid < 8) AV[tid] = (float)ansv[base + tid];
    __syncthreads();

    const int k = tid;
    const float4* wrow = (const float4*)(W1 + k * 384);

    float rs = 0.f;
#pragma unroll
    for (int j4 = 64; j4 < 96; ++j4) { float4 w = wrow[j4]; rs += w.x + w.y + w.z + w.w; }

    float acc[8];
    const float bk = b1[k];
#pragma unroll
    for (int r = 0; r < 8; ++r) acc[r] = bk + AV[r] * rs;

    for (int j4 = 0; j4 < 64; ++j4) {
        float4 w = wrow[j4];
#pragma unroll
        for (int r = 0; r < 8; ++r) {
            float4 x = ((const float4*)X[r])[j4];
            acc[r] = fmaf(x.x, w.x, acc[r]);
            acc[r] = fmaf(x.y, w.y, acc[r]);
            acc[r] = fmaf(x.z, w.z, acc[r]);
            acc[r] = fmaf(x.w, w.w, acc[r]);
        }
    }
#pragma unroll
    for (int r = 0; r < 8; ++r) g_le[(base + r) * DK + k] = acc[r];
}

// ------------------------------------------------------------------
// Kernel 2: hoisted per-step constants. (unchanged)
// ------------------------------------------------------------------
__global__ void pre_kernel(const int* __restrict__ eid, const int* __restrict__ itid,
                           const float* __restrict__ ex_table, const float* __restrict__ it_table,
                           const float* __restrict__ Wl, const float* __restrict__ bl,
                           const float* __restrict__ Wg, const float* __restrict__ bg,
                           const float* __restrict__ Wf, const float* __restrict__ bf,
                           const float* __restrict__ Wp, const float* __restrict__ bp)
{
    __shared__ float X[16][512];
    const int tid  = threadIdx.x;
    const int base = blockIdx.x * 16;

    for (int idx = tid; idx < 16 * 512; idx += 512) {
        int r = idx >> 9, c = idx & 511;
        int p = base + r;
        int b = p / NSTEP, t = p % NSTEP;
        float v;
        if (c < 128)      v = (t == 0) ? 0.f : g_le[(b * SEQ + t - 1) * DK + c];
        else if (c < 256) v = it_table[itid[b * SEQ + t + 1] * DK + (c - 128)];
        else if (c < 384) v = g_le[(b * SEQ + t) * DK + (c - 256)];
        else              v = ex_table[eid[b * SEQ + t + 1] * DK + (c - 384)];
        X[r][c] = v;
    }
    __syncthreads();

    const int g = tid >> 7, k = tid & 127;
    float acc[16];

    if (g <= 1) {
        const float* W = (g == 0) ? Wl : Wg;
        const float  bk = (g == 0) ? bl[k] : bg[k];
#pragma unroll
        for (int r = 0; r < 16; ++r) acc[r] = bk;
        const float4* wrow = (const float4*)(W + k * 512);
        for (int j4 = 0; j4 < 96; ++j4) {
            float4 w = wrow[j4];
#pragma unroll
            for (int r = 0; r < 16; ++r) {
                float4 x = ((const float4*)X[r])[j4];
                acc[r] = fmaf(x.x, w.x, acc[r]);
                acc[r] = fmaf(x.y, w.y, acc[r]);
                acc[r] = fmaf(x.z, w.z, acc[r]);
                acc[r] = fmaf(x.w, w.w, acc[r]);
            }
        }
        float* dst = (g == 0) ? g_Al : g_Ag;
#pragma unroll
        for (int r = 0; r < 16; ++r) dst[(base + r) * DK + k] = acc[r];
    } else if (g == 2) {
        const float bk = bf[k];
#pragma unroll
        for (int r = 0; r < 16; ++r) acc[r] = bk;
        const float4* wrow = (const float4*)(Wf + k * 384 + 256);
        for (int j4 = 0; j4 < 32; ++j4) {
            float4 w = wrow[j4];
#pragma unroll
            for (int r = 0; r < 16; ++r) {
                float4 x = ((const float4*)(X[r] + 128))[j4];
                acc[r] = fmaf(x.x, w.x, acc[r]);
                acc[r] = fmaf(x.y, w.y, acc[r]);
                acc[r] = fmaf(x.z, w.z, acc[r]);
                acc[r] = fmaf(x.w, w.w, acc[r]);
            }
        }
#pragma unroll
        for (int r = 0; r < 16; ++r) g_Af[(base + r) * DK + k] = acc[r];
    } else {
        const float bk = bp[k];
#pragma unroll
        for (int r = 0; r < 16; ++r) acc[r] = bk;
        const float4* wrow = (const float4*)(Wp + k * 256);
        for (int j4 = 0; j4 < 32; ++j4) {
            float4 w = wrow[j4];
#pragma unroll
            for (int r = 0; r < 16; ++r) {
                float4 x = ((const float4*)(X[r] + 384))[j4];
                acc[r] = fmaf(x.x, w.x, acc[r]);
                acc[r] = fmaf(x.y, w.y, acc[r]);
                acc[r] = fmaf(x.z, w.z, acc[r]);
                acc[r] = fmaf(x.w, w.w, acc[r]);
            }
        }
#pragma unroll
        for (int r = 0; r < 16; ++r) g_Ap[(base + r) * DK + k] = acc[r];
    }
}

// ------------------------------------------------------------------
// Kernel 3: recurrent loop.
// SMEM float offsets:
static constexpr int SM_H    = 0;                        // 64*132
static constexpr int SM_WT   = SM_H   + SKP * HST;       // 8448  (Wf0^T, swizzled, 128*128)
static constexpr int SM_WL2  = SM_WT  + DK * DK;         // 24832 (32*132)
static constexpr int SM_WG2  = SM_WL2 + 32 * WST;        // 29056
static constexpr int SM_WF1  = SM_WG2 + 32 * WST;        // 33280
static constexpr int SM_WP1  = SM_WF1 + 32 * WST;        // 37504
static constexpr int SM_RED  = SM_WP1 + 32 * WST;        // 41728 (16*128)
static constexpr int SM_MAIL = SM_RED + 16 * DK;         // 43776 (2*4*128)
static constexpr int SM_LGF  = SM_MAIL + 2 * 4 * DK;     // 44800 (2*128)
static constexpr int SM_CFF  = SM_LGF + 2 * DK;          // 45056 (2*128)
static constexpr int SM_HT   = SM_CFF + 2 * DK;          // 45312 (128)
static constexpr int SM_LGT  = SM_HT  + DK;              // 45440 (64)
static constexpr int SM_KV   = SM_LGT + 64;              // 45504 (2*64)
static constexpr int SM_BAR  = SM_KV  + 2 * SKP;         // 45632 (6 u64 = 12 floats)
static constexpr int SM_TOT  = SM_BAR + 16;
static constexpr int SMEM_BYTES = SM_TOT * 4;            // ~182.7 KB

// barrier byte offsets (relative to smem base)
#define BARH_B(buf)  ((SM_BAR * 4) + (buf) * 8)
#define BARLG_B(buf) ((SM_BAR * 4) + 16 + (buf) * 8)
#define BARCF_B(buf) ((SM_BAR * 4) + 32 + (buf) * 8)

__global__ void __cluster_dims__(CL, 1, 1) __launch_bounds__(NT, 1)
recur_kernel(const int* __restrict__ eid, const float* __restrict__ qmat,
             const float* __restrict__ Wl, const float* __restrict__ Wg,
             const float* __restrict__ Wf, const float* __restrict__ Wp,
             const float* __restrict__ h0, float* __restrict__ out)
{
    extern __shared__ float sm[];
    float* hS   = sm + SM_H;
    float* wT   = sm + SM_WT;
    float* wl2  = sm + SM_WL2;
    float* wg2  = sm + SM_WG2;
    float* wf1  = sm + SM_WF1;
    float* wp1  = sm + SM_WP1;
    float* red  = sm + SM_RED;
    float* mail = sm + SM_MAIL;
    float* LGf  = sm + SM_LGF;
    float* cff  = sm + SM_CFF;
    float* htil = sm + SM_HT;
    float* lgt  = sm + SM_LGT;
    float* kv   = sm + SM_KV;

    const unsigned sbase = smem_u32(sm);
    const int tid   = threadIdx.x;
    const int b     = blockIdx.x / CL;
    const int r     = (int)my_cluster_rank();
    const int sBase = r * SKP;

    // ---- barrier init ----
    if (tid == 0) {
        mbar_init(sbase + BARH_B(0), 512);  mbar_init(sbase + BARH_B(1), 512);
        mbar_init(sbase + BARLG_B(0), 128); mbar_init(sbase + BARLG_B(1), 128);
        mbar_init(sbase + BARCF_B(0), 128); mbar_init(sbase + BARCF_B(1), 128);
    }

    // ---- prologue loads ----
    // Wf0^T with 16B-unit XOR swizzle: element (j,k) -> wT[j*128 + ((v^(v>>3))<<2)+c2]
    for (int idx = tid; idx < DK * DK; idx += NT) {
        int j = idx >> 7, k = idx & 127;
        int v = k >> 2, c2 = k & 3;
        wT[j * DK + (((v ^ (v >> 3)) & 31) << 2) + c2] = Wf[k * 384 + j];
    }
    for (int idx = tid; idx < 32 * DK; idx += NT) {
        int row = idx >> 7, k = idx & 127;
        int gk = sBase / 2 + row;        // 32*r + row  (global output row for this rank)
        wl2[row * WST + k] = Wl[gk * 512 + 384 + k];
        wg2[row * WST + k] = Wg[gk * 512 + 384 + k];
        wf1[row * WST + k] = Wf[gk * 384 + 128 + k];
        wp1[row * WST + k] = Wp[gk * 256 + 128 + k];
    }
    for (int idx = tid; idx < SKP * DK; idx += NT) {
        int s = idx >> 7, k = idx & 127;
        hS[s * HST + k] = h0[(sBase + s) * DK + k];
    }
    if (tid < SKP) kv[tid] = qmat[eid[b * SEQ] * NSKILL + sBase + tid];  // kv buf 0 = step 0
    __syncthreads();
    cluster_sync_all();   // barriers + smem visible cluster-wide

    // ---- initial h_tilde partial push (exchange u=0 -> buffer 0) ----
    if (tid < DK) {
        float a = 0.f;
        for (int s = 0; s < SKP; ++s) a = fmaf(kv[s], hS[s * HST + tid], a);
        unsigned la = sbase + (SM_MAIL + (0 * 4 + r) * DK + tid) * 4;
#pragma unroll
        for (int rr = 0; rr < CL; ++rr) st_cluster_f32(mapa_rank(la, rr), a);
#pragma unroll
        for (int rr = 0; rr < CL; ++rr) arrive_cluster(mapa_rank(sbase + BARH_B(0), rr));
    }

    // thread roles
    const int kG = tid & 15;          // GEMM col group (8 cols)
    const int sG = tid >> 4;          // GEMM skill group (4 skills)
    const int v0 = kG * 2, v1 = kG * 2 + 1;
    const float* wp0 = wT + (((v0 ^ (v0 >> 3)) & 31) << 2);
    const float* wp1w = wT + (((v1 ^ (v1 >> 3)) & 31) << 2);
    const float* hrow0 = hS + (sG * 4) * HST;

    const int rowB = tid >> 2, qB = tid & 3;           // phase B: 64 rows x 4
    const float* wBp = ((rowB < 32) ? (wl2 + rowB * WST) : (wg2 + (rowB - 32) * WST)) + qB * 32;
    const int rowD = tid >> 3, octD = tid & 7;         // phase D / pred: 32 rows x 8

    for (int t = 0; t < NSTEP; ++t) {
        const int buf = t & 1;
        const unsigned ph = (unsigned)((t >> 1) & 1);
        const int ptA = (b * NSTEP + t) * DK;

        // ---- wait h_tilde exchange u=t; materialize htil ----
        wait_parity_cluster(sbase + BARH_B(buf), ph);
        if (tid < DK) {
            const float* m = mail + buf * 4 * DK + tid;
            htil[tid] = m[0] + m[DK] + m[2 * DK] + m[3 * DK];
        }
        __syncthreads();

        // ---- prediction for step t-1 (uses new h_tilde) ----
        if (t > 0) {
            float a = 0.f;
            const float* wfp = wp1 + rowD * WST + octD * 16;
            const float* hp  = htil + octD * 16;
#pragma unroll
            for (int j4 = 0; j4 < 4; ++j4) {
                float4 w = ((const float4*)wfp)[j4];
                float4 h = ((const float4*)hp)[j4];
                a = fmaf(h.x, w.x, a); a = fmaf(h.y, w.y, a);
                a = fmaf(h.z, w.z, a); a = fmaf(h.w, w.w, a);
            }
            a += __shfl_xor_sync(0xffffffffu, a, 1);
            a += __shfl_xor_sync(0xffffffffu, a, 2);
            a += __shfl_xor_sync(0xffffffffu, a, 4);
            if (octD == 0) {
                int k = r * 32 + rowD;
                out[(b * NSTEP + (t - 1)) * DK + k] =
                    sigm(a + g_Ap[(b * NSTEP + (t - 1)) * DK + k]);
            }
        }

        // ---- phase A: facc = h_pre @ Wf0^T  (packed f32x2) ----
        unsigned long long acc[4][4];
#pragma unroll
        for (int i = 0; i < 4; ++i)
#pragma unroll
            for (int p = 0; p < 4; ++p) acc[i][p] = 0ull;

#pragma unroll 4
        for (int j = 0; j < DK; ++j) {
            ulonglong2 wa = *(const ulonglong2*)(wp0 + j * DK);
            ulonglong2 wb = *(const ulonglong2*)(wp1w + j * DK);
#pragma unroll
            for (int i = 0; i < 4; ++i) {
                float h = hrow0[i * HST + j];
                unsigned long long h2 = f2pack(h, h);
                acc[i][0] = fma2(h2, wa.x, acc[i][0]);
                acc[i][1] = fma2(h2, wa.y, acc[i][1]);
                acc[i][2] = fma2(h2, wb.x, acc[i][2]);
                acc[i][3] = fma2(h2, wb.y, acc[i][3]);
            }
        }

        // ---- load kv_next (ping-pong buffer) ----
        if (tid < SKP) {
            kv[((t + 1) & 1) * SKP + tid] =
                qmat[eid[b * SEQ + t + 1] * NSKILL + sBase + tid];
        }

        // ---- phase B: lg/gate dot parts (rank's 32 rows each) ----
        {
            float a = 0.f;
            const float* hp = htil + qB * 32;
#pragma unroll
            for (int j4 = 0; j4 < 8; ++j4) {
                float4 w = ((const float4*)wBp)[j4];
                float4 h = ((const float4*)hp)[j4];
                a = fmaf(h.x, w.x, a); a = fmaf(h.y, w.y, a);
                a = fmaf(h.z, w.z, a); a = fmaf(h.w, w.w, a);
            }
            a += __shfl_xor_sync(0xffffffffu, a, 1);
            a += __shfl_xor_sync(0xffffffffu, a, 2);
            if (qB == 0) lgt[rowB] = a;
        }
        __syncthreads();

        // ---- phase C: LG (32 values per rank) -> push to all ranks ----
        if (tid < 32) {
            const int k = r * 32 + tid;
            float lgp = g_Al[ptA + k] + lgt[tid];
            float gtp = g_Ag[ptA + k] + lgt[32 + tid];
            float val = sigm(gtp) * sigm(2.f * lgp);   // gate*(tanh+1)/2
            unsigned la = sbase + (SM_LGF + buf * DK + k) * 4;
#pragma unroll
            for (int rr = 0; rr < CL; ++rr) st_cluster_f32(mapa_rank(la, rr), val);
#pragma unroll
            for (int rr = 0; rr < CL; ++rr) arrive_cluster(mapa_rank(sbase + BARLG_B(buf), rr));
        }
        wait_parity_cluster(sbase + BARLG_B(buf), ph);

        // ---- phase D: cf rows (rank's 32) -> push to all ranks ----
        {
            float a = 0.f;
            const float* wfp = wf1 + rowD * WST + octD * 16;
            const float* lp  = LGf + buf * DK + octD * 16;
#pragma unroll
            for (int j4 = 0; j4 < 4; ++j4) {
                float4 w = ((const float4*)wfp)[j4];
                float4 h = ((const float4*)lp)[j4];
                a = fmaf(h.x, w.x, a); a = fmaf(h.y, w.y, a);
                a = fmaf(h.z, w.z, a); a = fmaf(h.w, w.w, a);
            }
            a += __shfl_xor_sync(0xffffffffu, a, 1);
            a += __shfl_xor_sync(0xffffffffu, a, 2);
            a += __shfl_xor_sync(0xffffffffu, a, 4);
            if (octD == 0) {
                const int k = r * 32 + rowD;
                float val = a + g_Af[ptA + k];
                unsigned la = sbase + (SM_CFF + buf * DK + k) * 4;
#pragma unroll
                for (int rr = 0; rr < CL; ++rr) st_cluster_f32(mapa_rank(la, rr), val);
#pragma unroll
                for (int rr = 0; rr < CL; ++rr) arrive_cluster(mapa_rank(sbase + BARCF_B(buf), rr));
            }
        }
        wait_parity_cluster(sbase + BARCF_B(buf), ph);

        // ---- phase E: f, h update, partial h_tilde ----
        {
            const int k0 = kG * 8;
            float cf8[8], lg8[8];
#pragma unroll
            for (int c = 0; c < 8; ++c) {
                cf8[c] = cff[buf * DK + k0 + c];
                lg8[c] = LGf[buf * DK + k0 + c];
            }
            float pk[8];
#pragma unroll
            for (int c = 0; c < 8; ++c) pk[c] = 0.f;

            const float* kvC = kv + buf * SKP;
            const float* kvN = kv + ((t + 1) & 1) * SKP;
#pragma unroll
            for (int i = 0; i < 4; ++i) {
                const int s = sG * 4 + i;
                const float kt = kvC[s], kn = kvN[s];
                float* hr = hS + s * HST + k0;
                float4 h0v = *(const float4*)(hr);
                float4 h1v = *(const float4*)(hr + 4);
                float hv[8] = {h0v.x, h0v.y, h0v.z, h0v.w, h1v.x, h1v.y, h1v.z, h1v.w};
                float hn[8];
#pragma unroll
                for (int p = 0; p < 4; ++p) {
                    float2 fa = f2unpack(acc[i][p]);
                    float f0 = sigm(fa.x + cf8[2 * p]);
                    float f1 = sigm(fa.y + cf8[2 * p + 1]);
                    hn[2 * p]     = fmaf(f0, hv[2 * p],     kt * lg8[2 * p]);
                    hn[2 * p + 1] = fmaf(f1, hv[2 * p + 1], kt * lg8[2 * p + 1]);
                }
#pragma unroll
                for (int c = 0; c < 8; ++c) pk[c] = fmaf(kn, hn[c], pk[c]);
                *(float4*)(hr)     = make_float4(hn[0], hn[1], hn[2], hn[3]);
                *(float4*)(hr + 4) = make_float4(hn[4], hn[5], hn[6], hn[7]);
            }
            *(float4*)(red + sG * DK + k0)     = make_float4(pk[0], pk[1], pk[2], pk[3]);
            *(float4*)(red + sG * DK + k0 + 4) = make_float4(pk[4], pk[5], pk[6], pk[7]);
        }
        __syncthreads();

        // ---- phase F: CTA reduce + push h_tilde partials (exchange u=t+1) ----
        if (tid < DK) {
            float a = 0.f;
#pragma unroll
            for (int g2 = 0; g2 < 16; ++g2) a += red[g2 * DK + tid];
            const int nbuf = (t + 1) & 1;
            unsigned la = sbase + (SM_MAIL + (nbuf * 4 + r) * DK + tid) * 4;
#pragma unroll
            for (int rr = 0; rr < CL; ++rr) st_cluster_f32(mapa_rank(la, rr), a);
#pragma unroll
            for (int rr = 0; rr < CL; ++rr) arrive_cluster(mapa_rank(sbase + BARH_B(nbuf), rr));
        }
    }

    // ---- epilogue: final exchange (u=127) + prediction for t=126 ----
    wait_parity_cluster(sbase + BARH_B(1), (unsigned)((NSTEP >> 1) & 1));
    if (tid < DK) {
        const float* m = mail + 1 * 4 * DK + tid;
        htil[tid] = m[0] + m[DK] + m[2 * DK] + m[3 * DK];
    }
    __syncthreads();
    {
        float a = 0.f;
        const float* wfp = wp1 + rowD * WST + octD * 16;
        const float* hp  = htil + octD * 16;
#pragma unroll
        for (int j4 = 0; j4 < 4; ++j4) {
            float4 w = ((const float4*)wfp)[j4];
            float4 h = ((const float4*)hp)[j4];
            a = fmaf(h.x, w.x, a); a = fmaf(h.y, w.y, a);
            a = fmaf(h.z, w.z, a); a = fmaf(h.w, w.w, a);
        }
        a += __shfl_xor_sync(0xffffffffu, a, 1);
        a += __shfl_xor_sync(0xffffffffu, a, 2);
        a += __shfl_xor_sync(0xffffffffu, a, 4);
        if (octD == 0) {
            int k = r * 32 + rowD;
            out[(b * NSTEP + (NSTEP - 1)) * DK + k] =
                sigm(a + g_Ap[(b * NSTEP + (NSTEP - 1)) * DK + k]);
        }
    }
    cluster_sync_all();   // exit safety for in-flight DSMEM traffic
}

// ------------------------------------------------------------------
extern "C" void kernel_launch(void* const* d_in, const int* in_sizes, int n_in,
                              void* d_out, int out_size)
{
    const int*   eid      = (const int*)d_in[0];
    const int*   atid     = (const int*)d_in[1];
    const int*   itid     = (const int*)d_in[2];
    const int*   ansv     = (const int*)d_in[3];
    const float* qmat     = (const float*)d_in[4];
    const float* ex_table = (const float*)d_in[5];
    const float* at_table = (const float*)d_in[6];
    const float* it_table = (const float*)d_in[7];
    const float* W1       = (const float*)d_in[8];
    const float* b1       = (const float*)d_in[9];
    const float* Wl       = (const float*)d_in[10];
    const float* bl       = (const float*)d_in[11];
    const float* Wg       = (const float*)d_in[12];
    const float* bg       = (const float*)d_in[13];
    const float* Wf       = (const float*)d_in[14];
    const float* bf       = (const float*)d_in[15];
    const float* Wp       = (const float*)d_in[16];
    const float* bp       = (const float*)d_in[17];
    const float* h0       = (const float*)d_in[18];
    float* out = (float*)d_out;

    cudaFuncSetAttribute(recur_kernel, cudaFuncAttributeMaxDynamicSharedMemorySize, SMEM_BYTES);

    le_kernel<<<(BATCH * SEQ) / 8, 128>>>(eid, atid, ansv, ex_table, at_table, W1, b1);
    pre_kernel<<<(BATCH * NSTEP) / 16, 512>>>(eid, itid, ex_table, it_table,
                                              Wl, bl, Wg, bg, Wf, bf, Wp, bp);
    recur_kernel<<<BATCH * CL, NT, SMEM_BYTES>>>(eid, qmat, Wl, Wg, Wf, Wp, h0, out);
}

// round 4
// speedup vs baseline: 1.7430x; 1.2732x over previous
#include <cuda_runtime.h>
#include <cuda_bf16.h>

#define BATCH  32
#define SEQ    128
#define NSTEP  127
#define DK     128
#define NSKILL 256

#define CL   4      // cluster size (CTAs per batch)
#define SKP  64     // skills per CTA
#define NT   384    // 8 GEMM warps + 4 chain warps
#define HST  132    // padded h row stride (floats)
#define WST  132    // padded small-weight row stride (floats)

// ------------------------- device scratch -------------------------
__device__ float g_le[BATCH * SEQ * DK];
__device__ float g_Al[BATCH * NSTEP * DK];
__device__ float g_Ag[BATCH * NSTEP * DK];
__device__ float g_Af[BATCH * NSTEP * DK];
__device__ float g_Ap[BATCH * NSTEP * DK];

__device__ __forceinline__ float sigm(float x) { return 1.f / (1.f + __expf(-x)); }

// ---------- packed f32x2 helpers ----------
__device__ __forceinline__ unsigned long long fma2(unsigned long long a,
                                                   unsigned long long b,
                                                   unsigned long long c) {
    unsigned long long d;
    asm("fma.rn.f32x2 %0, %1, %2, %3;" : "=l"(d) : "l"(a), "l"(b), "l"(c));
    return d;
}
__device__ __forceinline__ unsigned long long f2pack(float x, float y) {
    unsigned long long u;
    asm("mov.b64 %0, {%1, %2};" : "=l"(u) : "f"(x), "f"(y));
    return u;
}
__device__ __forceinline__ unsigned long long f2dup(float x) {
    unsigned long long u;
    asm("mov.b64 %0, {%1, %1};" : "=l"(u) : "f"(x));
    return u;
}
__device__ __forceinline__ float2 f2unpack(unsigned long long u) {
    float2 r;
    asm("mov.b64 {%0, %1}, %2;" : "=f"(r.x), "=f"(r.y) : "l"(u));
    return r;
}

// ---------- cluster / mbarrier helpers ----------
__device__ __forceinline__ unsigned smem_u32(const void* p) {
    unsigned a;
    asm("{ .reg .u64 t; cvta.to.shared.u64 t, %1; cvt.u32.u64 %0, t; }" : "=r"(a) : "l"(p));
    return a;
}
__device__ __forceinline__ unsigned mapa_rank(unsigned a, int rank) {
    unsigned d;
    asm("mapa.shared::cluster.u32 %0, %1, %2;" : "=r"(d) : "r"(a), "r"(rank));
    return d;
}
__device__ __forceinline__ void st_cluster_f32(unsigned a, float v) {
    asm volatile("st.shared::cluster.f32 [%0], %1;" :: "r"(a), "f"(v) : "memory");
}
__device__ __forceinline__ void mbar_init(unsigned a, unsigned cnt) {
    asm volatile("mbarrier.init.shared.b64 [%0], %1;" :: "r"(a), "r"(cnt) : "memory");
}
__device__ __forceinline__ void arrive_cluster(unsigned a) {
    asm volatile("mbarrier.arrive.release.cluster.shared::cluster.b64 _, [%0];"
                 :: "r"(a) : "memory");
}
__device__ __forceinline__ void wait_parity_cluster(unsigned a, unsigned ph) {
    unsigned done;
    asm volatile(
        "{\n\t.reg .pred p;\n\t"
        "mbarrier.try_wait.parity.acquire.cluster.shared::cta.b64 p, [%1], %2;\n\t"
        "selp.b32 %0, 1, 0, p;\n\t}"
        : "=r"(done) : "r"(a), "r"(ph) : "memory");
    if (!done) {
        asm volatile(
            "{\n\t.reg .pred P1;\n\t"
            "W_%=:\n\t"
            "mbarrier.try_wait.parity.acquire.cluster.shared::cta.b64 P1, [%0], %1, 0x989680;\n\t"
            "@P1 bra.uni D_%=;\n\t"
            "bra.uni W_%=;\n\t"
            "D_%=:\n\t}"
            :: "r"(a), "r"(ph) : "memory");
    }
}
__device__ __forceinline__ void cluster_sync_all() {
    asm volatile("barrier.cluster.arrive.aligned;" ::: "memory");
    asm volatile("barrier.cluster.wait.aligned;" ::: "memory");
}
__device__ __forceinline__ unsigned my_cluster_rank() {
    unsigned r;
    asm("mov.u32 %0, %%cluster_ctarank;" : "=r"(r));
    return r;
}
__device__ __forceinline__ void bar_sync(int id, int n) {
    asm volatile("bar.sync %0, %1;" :: "r"(id), "r"(n) : "memory");
}

// ------------------------------------------------------------------
// Kernel 1: le[b,s,:] = [ex | at | ans] @ W1^T + b1
// ------------------------------------------------------------------
__global__ void le_kernel(const int* __restrict__ eid, const int* __restrict__ atid,
                          const int* __restrict__ ansv,
                          const float* __restrict__ ex_table, const float* __restrict__ at_table,
                          const float* __restrict__ W1, const float* __restrict__ b1)
{
    __shared__ float X[8][256];
    __shared__ float AV[8];
    const int tid  = threadIdx.x;
    const int base = blockIdx.x * 8;

    for (int idx = tid; idx < 8 * 256; idx += 128) {
        int r = idx >> 8, c = idx & 255;
        int p = base + r;
        float v;
        if (c < 128) v = ex_table[eid[p] * DK + c];
        else         v = at_table[atid[p] * DK + (c - 128)];
        X[r][c] = v;
    }
    if (tid < 8) AV[tid] = (float)ansv[base + tid];
    __syncthreads();

    const int k = tid;
    const float4* wrow = (const float4*)(W1 + k * 384);

    float rs = 0.f;
#pragma unroll
    for (int j4 = 64; j4 < 96; ++j4) { float4 w = wrow[j4]; rs += w.x + w.y + w.z + w.w; }

    float acc[8];
    const float bk = b1[k];
#pragma unroll
    for (int r = 0; r < 8; ++r) acc[r] = bk + AV[r] * rs;

    for (int j4 = 0; j4 < 64; ++j4) {
        float4 w = wrow[j4];
#pragma unroll
        for (int r = 0; r < 8; ++r) {
            float4 x = ((const float4*)X[r])[j4];
            acc[r] = fmaf(x.x, w.x, acc[r]);
            acc[r] = fmaf(x.y, w.y, acc[r]);
            acc[r] = fmaf(x.z, w.z, acc[r]);
            acc[r] = fmaf(x.w, w.w, acc[r]);
        }
    }
#pragma unroll
    for (int r = 0; r < 8; ++r) g_le[(base + r) * DK + k] = acc[r];
}

// ------------------------------------------------------------------
// Kernel 2: hoisted per-step constants.
// ------------------------------------------------------------------
__global__ void pre_kernel(const int* __restrict__ eid, const int* __restrict__ itid,
                           const float* __restrict__ ex_table, const float* __restrict__ it_table,
                           const float* __restrict__ Wl, const float* __restrict__ bl,
                           const float* __restrict__ Wg, const float* __restrict__ bg,
                           const float* __restrict__ Wf, const float* __restrict__ bf,
                           const float* __restrict__ Wp, const float* __restrict__ bp)
{
    __shared__ float X[16][512];
    const int tid  = threadIdx.x;
    const int base = blockIdx.x * 16;

    for (int idx = tid; idx < 16 * 512; idx += 512) {
        int r = idx >> 9, c = idx & 511;
        int p = base + r;
        int b = p / NSTEP, t = p % NSTEP;
        float v;
        if (c < 128)      v = (t == 0) ? 0.f : g_le[(b * SEQ + t - 1) * DK + c];
        else if (c < 256) v = it_table[itid[b * SEQ + t + 1] * DK + (c - 128)];
        else if (c < 384) v = g_le[(b * SEQ + t) * DK + (c - 256)];
        else              v = ex_table[eid[b * SEQ + t + 1] * DK + (c - 384)];
        X[r][c] = v;
    }
    __syncthreads();

    const int g = tid >> 7, k = tid & 127;
    float acc[16];

    if (g <= 1) {
        const float* W = (g == 0) ? Wl : Wg;
        const float  bk = (g == 0) ? bl[k] : bg[k];
#pragma unroll
        for (int r = 0; r < 16; ++r) acc[r] = bk;
        const float4* wrow = (const float4*)(W + k * 512);
        for (int j4 = 0; j4 < 96; ++j4) {
            float4 w = wrow[j4];
#pragma unroll
            for (int r = 0; r < 16; ++r) {
                float4 x = ((const float4*)X[r])[j4];
                acc[r] = fmaf(x.x, w.x, acc[r]);
                acc[r] = fmaf(x.y, w.y, acc[r]);
                acc[r] = fmaf(x.z, w.z, acc[r]);
                acc[r] = fmaf(x.w, w.w, acc[r]);
            }
        }
        float* dst = (g == 0) ? g_Al : g_Ag;
#pragma unroll
        for (int r = 0; r < 16; ++r) dst[(base + r) * DK + k] = acc[r];
    } else if (g == 2) {
        const float bk = bf[k];
#pragma unroll
        for (int r = 0; r < 16; ++r) acc[r] = bk;
        const float4* wrow = (const float4*)(Wf + k * 384 + 256);
        for (int j4 = 0; j4 < 32; ++j4) {
            float4 w = wrow[j4];
#pragma unroll
            for (int r = 0; r < 16; ++r) {
                float4 x = ((const float4*)(X[r] + 128))[j4];
                acc[r] = fmaf(x.x, w.x, acc[r]);
                acc[r] = fmaf(x.y, w.y, acc[r]);
                acc[r] = fmaf(x.z, w.z, acc[r]);
                acc[r] = fmaf(x.w, w.w, acc[r]);
            }
        }
#pragma unroll
        for (int r = 0; r < 16; ++r) g_Af[(base + r) * DK + k] = acc[r];
    } else {
        const float bk = bp[k];
#pragma unroll
        for (int r = 0; r < 16; ++r) acc[r] = bk;
        const float4* wrow = (const float4*)(Wp + k * 256);
        for (int j4 = 0; j4 < 32; ++j4) {
            float4 w = wrow[j4];
#pragma unroll
            for (int r = 0; r < 16; ++r) {
                float4 x = ((const float4*)(X[r] + 384))[j4];
                acc[r] = fmaf(x.x, w.x, acc[r]);
                acc[r] = fmaf(x.y, w.y, acc[r]);
                acc[r] = fmaf(x.z, w.z, acc[r]);
                acc[r] = fmaf(x.w, w.w, acc[r]);
            }
        }
#pragma unroll
        for (int r = 0; r < 16; ++r) g_Ap[(base + r) * DK + k] = acc[r];
    }
}

// ------------------------------------------------------------------
// Kernel 3: warp-specialized recurrent loop.
//   warps 0-7 (256 thr): f-GEMM + h update + h_tilde push
//   warps 8-11 (128 thr): htil materialize, lg/gate/cf matvecs, LG/cf push, preds
// ------------------------------------------------------------------
static constexpr int SM_H    = 0;                        // 64*132
static constexpr int SM_WS   = SM_H   + SKP * HST;       // 8448  wS[j*128+c] = Wf0^T
static constexpr int SM_WL2  = SM_WS  + DK * DK;         // 24832
static constexpr int SM_WG2  = SM_WL2 + 32 * WST;        // 29056
static constexpr int SM_WF1  = SM_WG2 + 32 * WST;        // 33280
static constexpr int SM_WP1  = SM_WF1 + 32 * WST;        // 37504
static constexpr int SM_MAIL = SM_WP1 + 32 * WST;        // 41728  (2 bufs * 4 ranks * 128)
static constexpr int SM_LGF  = SM_MAIL + 2 * CL * DK;    // 42752  (2*128)
static constexpr int SM_CFF  = SM_LGF + 2 * DK;          // 43008  (2*128)
static constexpr int SM_HT   = SM_CFF + 2 * DK;          // 43264  (128)
static constexpr int SM_LGT  = SM_HT  + DK;              // 43392  (64)
static constexpr int SM_KV   = SM_LGT + 64;              // 43456  (2*64)
static constexpr int SM_BAR  = SM_KV  + 2 * SKP;         // 43584  (6 u64)
static constexpr int SM_TOT  = SM_BAR + 16;
static constexpr int SMEM_BYTES = SM_TOT * 4;            // ~170.3 KB

#define BARH_B(buf)  ((SM_BAR * 4) + (buf) * 8)
#define BARLG_B(buf) ((SM_BAR * 4) + 16 + (buf) * 8)
#define BARCF_B(buf) ((SM_BAR * 4) + 32 + (buf) * 8)

__global__ void __cluster_dims__(CL, 1, 1) __launch_bounds__(NT, 1)
recur_kernel(const int* __restrict__ eid, const float* __restrict__ qmat,
             const float* __restrict__ Wl, const float* __restrict__ Wg,
             const float* __restrict__ Wf, const float* __restrict__ Wp,
             const float* __restrict__ h0, float* __restrict__ out)
{
    extern __shared__ float sm[];
    float* hS   = sm + SM_H;
    float* wS   = sm + SM_WS;
    float* wl2  = sm + SM_WL2;
    float* wg2  = sm + SM_WG2;
    float* wf1  = sm + SM_WF1;
    float* wp1  = sm + SM_WP1;
    float* mail = sm + SM_MAIL;
    float* LGf  = sm + SM_LGF;
    float* cff  = sm + SM_CFF;
    float* htil = sm + SM_HT;
    float* lgt  = sm + SM_LGT;
    float* kv   = sm + SM_KV;

    const unsigned sbase = smem_u32(sm);
    const int tid   = threadIdx.x;
    const int b     = blockIdx.x / CL;
    const int r     = (int)my_cluster_rank();
    const int sBase = r * SKP;

    if (tid == 0) {
        mbar_init(sbase + BARH_B(0), 128);  mbar_init(sbase + BARH_B(1), 128);
        mbar_init(sbase + BARLG_B(0), 128); mbar_init(sbase + BARLG_B(1), 128);
        mbar_init(sbase + BARCF_B(0), 128); mbar_init(sbase + BARCF_B(1), 128);
    }

    // ---- prologue loads ----
    // wS[j][c] = Wf[c*384 + j]  (Wf0^T, row-major over j, 512B rows)
    for (int idx = tid; idx < DK * DK; idx += NT) {
        int j = idx >> 7, c = idx & 127;
        wS[idx] = Wf[c * 384 + j];
    }
    for (int idx = tid; idx < 32 * DK; idx += NT) {
        int row = idx >> 7, k = idx & 127;
        int gk = r * 32 + row;
        wl2[row * WST + k] = Wl[gk * 512 + 384 + k];
        wg2[row * WST + k] = Wg[gk * 512 + 384 + k];
        wf1[row * WST + k] = Wf[gk * 384 + 128 + k];
        wp1[row * WST + k] = Wp[gk * 256 + 128 + k];
    }
    for (int idx = tid; idx < SKP * DK; idx += NT) {
        int s = idx >> 7, k = idx & 127;
        hS[s * HST + k] = h0[(sBase + s) * DK + k];
    }
    if (tid < SKP) kv[tid] = qmat[eid[b * SEQ] * NSKILL + sBase + tid];
    __syncthreads();

    // initial h_tilde partial -> mail buf0 (plain cluster stores + cluster sync)
    if (tid >= 256) {
        const int col = tid - 256;
        float a = 0.f;
        for (int s = 0; s < SKP; ++s) a = fmaf(kv[s], hS[s * HST + col], a);
        unsigned la = sbase + (SM_MAIL + r * DK + col) * 4;
#pragma unroll
        for (int rr = 0; rr < CL; ++rr) st_cluster_f32(mapa_rank(la, rr), a);
    }
    cluster_sync_all();

    if (tid < 256) {
        // ================= GEMM warps =================
        const int w    = tid >> 5;
        const int lane = tid & 31;
        const int cL   = lane & 3;
        const int sL   = lane >> 2;
        const int c0   = w * 16 + cL * 4;
        const float* hbase = hS + sL * HST;
        int phLG[2] = {0, 0}, phCF[2] = {0, 0};

        for (int t = 0; t < NSTEP; ++t) {
            const int buf = t & 1, nbuf = buf ^ 1;

            // ---- A: facc[s][c] = sum_j h[s][j] * Wf0[c][j] ----
            unsigned long long acc[8][2];
#pragma unroll
            for (int i = 0; i < 8; ++i) { acc[i][0] = 0ull; acc[i][1] = 0ull; }

#pragma unroll 2
            for (int jj = 0; jj < DK; jj += 4) {
                float4 w0 = *(const float4*)(wS + (jj + 0) * DK + c0);
                float4 w1 = *(const float4*)(wS + (jj + 1) * DK + c0);
                float4 w2 = *(const float4*)(wS + (jj + 2) * DK + c0);
                float4 w3 = *(const float4*)(wS + (jj + 3) * DK + c0);
                unsigned long long wp00 = f2pack(w0.x, w0.y), wp01 = f2pack(w0.z, w0.w);
                unsigned long long wp10 = f2pack(w1.x, w1.y), wp11 = f2pack(w1.z, w1.w);
                unsigned long long wp20 = f2pack(w2.x, w2.y), wp21 = f2pack(w2.z, w2.w);
                unsigned long long wp30 = f2pack(w3.x, w3.y), wp31 = f2pack(w3.z, w3.w);
#pragma unroll
                for (int i = 0; i < 8; ++i) {
                    float4 h = *(const float4*)(hbase + i * (8 * HST) + jj);
                    unsigned long long hx = f2dup(h.x), hy = f2dup(h.y);
                    unsigned long long hz = f2dup(h.z), hw = f2dup(h.w);
                    acc[i][0] = fma2(hx, wp00, acc[i][0]); acc[i][1] = fma2(hx, wp01, acc[i][1]);
                    acc[i][0] = fma2(hy, wp10, acc[i][0]); acc[i][1] = fma2(hy, wp11, acc[i][1]);
                    acc[i][0] = fma2(hz, wp20, acc[i][0]); acc[i][1] = fma2(hz, wp21, acc[i][1]);
                    acc[i][0] = fma2(hw, wp30, acc[i][0]); acc[i][1] = fma2(hw, wp31, acc[i][1]);
                }
            }

            // ---- wait for LG + cf (chain produces them under the GEMM shadow) ----
            wait_parity_cluster(sbase + BARLG_B(buf), (unsigned)phLG[buf]); phLG[buf] ^= 1;
            wait_parity_cluster(sbase + BARCF_B(buf), (unsigned)phCF[buf]); phCF[buf] ^= 1;

            // ---- E: f, h update, partial h_tilde ----
            float4 cf4 = *(const float4*)(cff + buf * DK + c0);
            float4 lg4 = *(const float4*)(LGf + buf * DK + c0);
            float pk0 = 0.f, pk1 = 0.f, pk2 = 0.f, pk3 = 0.f;
#pragma unroll
            for (int i = 0; i < 8; ++i) {
                const int s = sL + 8 * i;
                const float kt = kv[buf * SKP + s];
                const float kn = kv[nbuf * SKP + s];
                float* hr = hS + s * HST + c0;
                float4 hv = *(const float4*)hr;
                float2 fa0 = f2unpack(acc[i][0]);
                float2 fa1 = f2unpack(acc[i][1]);
                float f0 = sigm(fa0.x + cf4.x);
                float f1 = sigm(fa0.y + cf4.y);
                float f2v = sigm(fa1.x + cf4.z);
                float f3 = sigm(fa1.y + cf4.w);
                float n0 = fmaf(f0, hv.x, kt * lg4.x);
                float n1 = fmaf(f1, hv.y, kt * lg4.y);
                float n2 = fmaf(f2v, hv.z, kt * lg4.z);
                float n3 = fmaf(f3, hv.w, kt * lg4.w);
                *(float4*)hr = make_float4(n0, n1, n2, n3);
                pk0 = fmaf(kn, n0, pk0); pk1 = fmaf(kn, n1, pk1);
                pk2 = fmaf(kn, n2, pk2); pk3 = fmaf(kn, n3, pk3);
            }
            // reduce over sL (xor 4,8,16); shfl also orders all lanes' reads
            // before the sL==0 lanes' release-arrives below.
#pragma unroll
            for (int m = 4; m <= 16; m <<= 1) {
                pk0 += __shfl_xor_sync(0xffffffffu, pk0, m);
                pk1 += __shfl_xor_sync(0xffffffffu, pk1, m);
                pk2 += __shfl_xor_sync(0xffffffffu, pk2, m);
                pk3 += __shfl_xor_sync(0xffffffffu, pk3, m);
            }
            if (sL == 0) {
                unsigned la = sbase + (SM_MAIL + (nbuf * CL + r) * DK + c0) * 4;
#pragma unroll
                for (int rr = 0; rr < CL; ++rr) {
                    unsigned ra = mapa_rank(la, rr);
                    st_cluster_f32(ra,      pk0);
                    st_cluster_f32(ra + 4,  pk1);
                    st_cluster_f32(ra + 8,  pk2);
                    st_cluster_f32(ra + 12, pk3);
                }
#pragma unroll
                for (int rr = 0; rr < CL; ++rr)
                    arrive_cluster(mapa_rank(sbase + BARH_B(nbuf), rr));
            }
            bar_sync(1, 256);   // hS fully updated before next A
        }
    } else {
        // ================= chain warps (128 threads) =================
        const int tc   = tid - 256;
        const int rowB = tc >> 1, qB = tc & 1;
        const int rowD = tc >> 2, qD = tc & 3;
        const float* wB = ((rowB < 32) ? (wl2 + rowB * WST) : (wg2 + (rowB - 32) * WST)) + qB * 64;
        int phH[2] = {0, 0}, phLG[2] = {0, 0};

        for (int t = 0; t < NSTEP; ++t) {
            const int buf = t & 1, nbuf = buf ^ 1;
            const int ptA = (b * NSTEP + t) * DK;

            // ---- htil materialize (exchange u=t) ----
            if (t > 0) { wait_parity_cluster(sbase + BARH_B(buf), (unsigned)phH[buf]); phH[buf] ^= 1; }
            {
                const float* m = mail + buf * CL * DK + tc;
                htil[tc] = m[0] + m[DK] + m[2 * DK] + m[3 * DK];
            }
            bar_sync(2, 128);

            // ---- kv_next (by the cf-arriving threads so release covers it) ----
            if (qD == 0) {
                const int e = eid[b * SEQ + t + 1] * NSKILL + sBase;
                kv[nbuf * SKP + rowD]      = qmat[e + rowD];
                kv[nbuf * SKP + 32 + rowD] = qmat[e + 32 + rowD];
            }

            // ---- B: lg/gate partial dots (own rank's 32 rows each) ----
            {
                float a = 0.f;
                const float* hp = htil + qB * 64;
#pragma unroll
                for (int j4 = 0; j4 < 16; ++j4) {
                    float4 w = ((const float4*)wB)[j4];
                    float4 h = ((const float4*)hp)[j4];
                    a = fmaf(h.x, w.x, a); a = fmaf(h.y, w.y, a);
                    a = fmaf(h.z, w.z, a); a = fmaf(h.w, w.w, a);
                }
                a += __shfl_xor_sync(0xffffffffu, a, 1);
                if (qB == 0) lgt[rowB] = a;
            }
            bar_sync(2, 128);

            // ---- C: LG values -> push to all ranks ----
            if (tc < 32) {
                const int k = r * 32 + tc;
                float lgp = g_Al[ptA + k] + lgt[tc];
                float gtp = g_Ag[ptA + k] + lgt[32 + tc];
                float val = sigm(gtp) * sigm(2.f * lgp);
                unsigned la = sbase + (SM_LGF + buf * DK + k) * 4;
#pragma unroll
                for (int rr = 0; rr < CL; ++rr) st_cluster_f32(mapa_rank(la, rr), val);
#pragma unroll
                for (int rr = 0; rr < CL; ++rr)
                    arrive_cluster(mapa_rank(sbase + BARLG_B(buf), rr));
            }

            // ---- prediction for step t-1 (independent of LG/cf) ----
            if (t > 0) {
                float a = 0.f;
                const float* wf = wp1 + rowD * WST + qD * 32;
                const float* hp = htil + qD * 32;
#pragma unroll
                for (int j4 = 0; j4 < 8; ++j4) {
                    float4 w = ((const float4*)wf)[j4];
                    float4 h = ((const float4*)hp)[j4];
                    a = fmaf(h.x, w.x, a); a = fmaf(h.y, w.y, a);
                    a = fmaf(h.z, w.z, a); a = fmaf(h.w, w.w, a);
                }
                a += __shfl_xor_sync(0xffffffffu, a, 1);
                a += __shfl_xor_sync(0xffffffffu, a, 2);
                if (qD == 0) {
                    const int k = r * 32 + rowD;
                    out[(b * NSTEP + (t - 1)) * DK + k] =
                        sigm(a + g_Ap[(b * NSTEP + (t - 1)) * DK + k]);
                }
            }

            // ---- D: cf rows -> push to all ranks ----
            wait_parity_cluster(sbase + BARLG_B(buf), (unsigned)phLG[buf]); phLG[buf] ^= 1;
            {
                float a = 0.f;
                const float* wf = wf1 + rowD * WST + qD * 32;
                const float* lp = LGf + buf * DK + qD * 32;
#pragma unroll
                for (int j4 = 0; j4 < 8; ++j4) {
                    float4 w = ((const float4*)wf)[j4];
                    float4 h = ((const float4*)lp)[j4];
                    a = fmaf(h.x, w.x, a); a = fmaf(h.y, w.y, a);
                    a = fmaf(h.z, w.z, a); a = fmaf(h.w, w.w, a);
                }
                a += __shfl_xor_sync(0xffffffffu, a, 1);
                a += __shfl_xor_sync(0xffffffffu, a, 2);
                if (qD == 0) {
                    const int k = r * 32 + rowD;
                    float val = a + g_Af[ptA + k];
                    unsigned la = sbase + (SM_CFF + buf * DK + k) * 4;
#pragma unroll
                    for (int rr = 0; rr < CL; ++rr) st_cluster_f32(mapa_rank(la, rr), val);
#pragma unroll
                    for (int rr = 0; rr < CL; ++rr)
                        arrive_cluster(mapa_rank(sbase + BARCF_B(buf), rr));
                }
            }
        }

        // ---- epilogue: exchange u=NSTEP, prediction for t = NSTEP-1 ----
        wait_parity_cluster(sbase + BARH_B(NSTEP & 1), (unsigned)phH[NSTEP & 1]);
        {
            const float* m = mail + (NSTEP & 1) * CL * DK + tc;
            htil[tc] = m[0] + m[DK] + m[2 * DK] + m[3 * DK];
        }
        bar_sync(2, 128);
        {
            float a = 0.f;
            const float* wf = wp1 + rowD * WST + qD * 32;
            const float* hp = htil + qD * 32;
#pragma unroll
            for (int j4 = 0; j4 < 8; ++j4) {
                float4 w = ((const float4*)wf)[j4];
                float4 h = ((const float4*)hp)[j4];
                a = fmaf(h.x, w.x, a); a = fmaf(h.y, w.y, a);
                a = fmaf(h.z, w.z, a); a = fmaf(h.w, w.w, a);
            }
            a += __shfl_xor_sync(0xffffffffu, a, 1);
            a += __shfl_xor_sync(0xffffffffu, a, 2);
            if (qD == 0) {
                const int k = r * 32 + rowD;
                out[(b * NSTEP + (NSTEP - 1)) * DK + k] =
                    sigm(a + g_Ap[(b * NSTEP + (NSTEP - 1)) * DK + k]);
            }
        }
    }

    cluster_sync_all();   // exit safety for in-flight DSMEM traffic
}

// ------------------------------------------------------------------
extern "C" void kernel_launch(void* const* d_in, const int* in_sizes, int n_in,
                              void* d_out, int out_size)
{
    const int*   eid      = (const int*)d_in[0];
    const int*   atid     = (const int*)d_in[1];
    const int*   itid     = (const int*)d_in[2];
    const int*   ansv     = (const int*)d_in[3];
    const float* qmat     = (const float*)d_in[4];
    const float* ex_table = (const float*)d_in[5];
    const float* at_table = (const float*)d_in[6];
    const float* it_table = (const float*)d_in[7];
    const float* W1       = (const float*)d_in[8];
    const float* b1       = (const float*)d_in[9];
    const float* Wl       = (const float*)d_in[10];
    const float* bl       = (const float*)d_in[11];
    const float* Wg       = (const float*)d_in[12];
    const float* bg       = (const float*)d_in[13];
    const float* Wf       = (const float*)d_in[14];
    const float* bf       = (const float*)d_in[15];
    const float* Wp       = (const float*)d_in[16];
    const float* bp       = (const float*)d_in[17];
    const float* h0       = (const float*)d_in[18];
    float* out = (float*)d_out;

    cudaFuncSetAttribute(recur_kernel, cudaFuncAttributeMaxDynamicSharedMemorySize, SMEM_BYTES);

    le_kernel<<<(BATCH * SEQ) / 8, 128>>>(eid, atid, ansv, ex_table, at_table, W1, b1);
    pre_kernel<<<(BATCH * NSTEP) / 16, 512>>>(eid, itid, ex_table, it_table,
                                              Wl, bl, Wg, bg, Wf, bf, Wp, bp);
    recur_kernel<<<BATCH * CL, NT, SMEM_BYTES>>>(eid, qmat, Wl, Wg, Wf, Wp, h0, out);
}